// round 5
// baseline (speedup 1.0000x reference)
#include <cuda_runtime.h>

#define BATCH 32768
#define NIMG  5
#define DIM   512
#define DCAT  600
#define M5    (BATCH * NIMG)

// Scratch (device globals — no runtime allocation allowed)
__device__ float g_c[BATCH * DCAT];     // conv concat [N,600]
__device__ float g_h[BATCH * DCAT];     // relu(fc1)   [N,600]
__device__ float g_ci[BATCH * DIM];     // fc2 out     [N,512]
__device__ float g_u[BATCH * DIM];      // ci@fc0_w[512:] + fc0_b  [N,512]
__device__ float g_score[M5];           // pre-bias scores [N*5]

// ---------------------------------------------------------------------------
// Conv block as GEMM with fused relu + max over T sliding windows.
// ---------------------------------------------------------------------------
__global__ __launch_bounds__(256) void conv_gemm(
    const float* __restrict__ feats, const float* __restrict__ W,
    const float* __restrict__ bias, int KD, int T, int coff)
{
    __shared__ float As[16][64];
    __shared__ float Bs[16][64];
    const int tid = threadIdx.x;
    const int tx = tid & 15, ty = tid >> 4;
    const int bm0 = blockIdx.x * 64;
    const int bn0 = blockIdx.y * 64;

    const int aRow = tid >> 2;          // 0..63
    const int aK   = (tid & 3) * 4;     // 0,4,8,12
    const int chL  = tid >> 2;          // local channel 0..63
    const int wK   = (tid & 3) * 4;
    const int ch   = bn0 + chL;

    float vmax[4][4];
#pragma unroll
    for (int i = 0; i < 4; i++)
#pragma unroll
        for (int j = 0; j < 4; j++) vmax[i][j] = 0.f;

    float bcol[4];
#pragma unroll
    for (int j = 0; j < 4; j++) {
        int c = bn0 + tx * 4 + j;
        bcol[j] = (c < 200) ? bias[c] : 0.f;
    }

    for (int t = 0; t < T; ++t) {
        float acc[4][4];
#pragma unroll
        for (int i = 0; i < 4; i++)
#pragma unroll
            for (int j = 0; j < 4; j++) acc[i][j] = 0.f;

        const float* Ab = feats + (size_t)(bm0 + aRow) * (NIMG * DIM) + t * DIM + aK;
        const float* Wb = W + (size_t)ch * KD + wK;

        for (int k0 = 0; k0 < KD; k0 += 16) {
            float4 av = *(const float4*)(Ab + k0);
            As[aK + 0][aRow] = av.x; As[aK + 1][aRow] = av.y;
            As[aK + 2][aRow] = av.z; As[aK + 3][aRow] = av.w;
            float4 wv = make_float4(0.f, 0.f, 0.f, 0.f);
            if (ch < 200) wv = *(const float4*)(Wb + k0);
            Bs[wK + 0][chL] = wv.x; Bs[wK + 1][chL] = wv.y;
            Bs[wK + 2][chL] = wv.z; Bs[wK + 3][chL] = wv.w;
            __syncthreads();
#pragma unroll
            for (int kk = 0; kk < 16; kk++) {
                float4 a = *(const float4*)&As[kk][ty * 4];
                float4 b = *(const float4*)&Bs[kk][tx * 4];
                float ar[4] = {a.x, a.y, a.z, a.w};
                float br[4] = {b.x, b.y, b.z, b.w};
#pragma unroll
                for (int i = 0; i < 4; i++)
#pragma unroll
                    for (int j = 0; j < 4; j++) acc[i][j] += ar[i] * br[j];
            }
            __syncthreads();
        }
#pragma unroll
        for (int i = 0; i < 4; i++)
#pragma unroll
            for (int j = 0; j < 4; j++)
                vmax[i][j] = fmaxf(vmax[i][j], acc[i][j] + bcol[j]);
    }

#pragma unroll
    for (int i = 0; i < 4; i++) {
        int m = bm0 + ty * 4 + i;
#pragma unroll
        for (int j = 0; j < 4; j++) {
            int c = bn0 + tx * 4 + j;
            if (c < 200) g_c[(size_t)m * DCAT + coff + c] = vmax[i][j];
        }
    }
}

// ---------------------------------------------------------------------------
// Generic fp32 GEMM: C = op(A[M,K] @ B[K,N] + bias)
// ---------------------------------------------------------------------------
__global__ __launch_bounds__(256) void fc_gemm(
    const float* __restrict__ A, int lda,
    const float* __restrict__ B, int ldb,
    const float* __restrict__ bias,
    float* __restrict__ C, int ldc,
    int N, int K, int do_relu)
{
    __shared__ float As[16][64];
    __shared__ float Bs[16][64];
    const int tid = threadIdx.x;
    const int tx = tid & 15, ty = tid >> 4;
    const int bm0 = blockIdx.x * 64;
    const int bn0 = blockIdx.y * 64;

    const int aRow = tid >> 2;
    const int aK   = (tid & 3) * 4;
    const int bK   = tid >> 4;          // 0..15
    const int bN   = (tid & 15) * 4;
    const int bcol = bn0 + bN;

    float acc[4][4];
#pragma unroll
    for (int i = 0; i < 4; i++)
#pragma unroll
        for (int j = 0; j < 4; j++) acc[i][j] = 0.f;

    const float* Ab = A + (size_t)(bm0 + aRow) * lda + aK;

    for (int k0 = 0; k0 < K; k0 += 16) {
        float4 av = make_float4(0.f, 0.f, 0.f, 0.f);
        if (k0 + aK < K) av = *(const float4*)(Ab + k0);
        As[aK + 0][aRow] = av.x; As[aK + 1][aRow] = av.y;
        As[aK + 2][aRow] = av.z; As[aK + 3][aRow] = av.w;

        float4 bv = make_float4(0.f, 0.f, 0.f, 0.f);
        if ((k0 + bK < K) && (bcol < N))
            bv = *(const float4*)(B + (size_t)(k0 + bK) * ldb + bcol);
        *(float4*)&Bs[bK][bN] = bv;
        __syncthreads();
#pragma unroll
        for (int kk = 0; kk < 16; kk++) {
            float4 a = *(const float4*)&As[kk][ty * 4];
            float4 b = *(const float4*)&Bs[kk][tx * 4];
            float ar[4] = {a.x, a.y, a.z, a.w};
            float br[4] = {b.x, b.y, b.z, b.w};
#pragma unroll
            for (int i = 0; i < 4; i++)
#pragma unroll
                for (int j = 0; j < 4; j++) acc[i][j] += ar[i] * br[j];
        }
        __syncthreads();
    }

#pragma unroll
    for (int i = 0; i < 4; i++) {
        int m = bm0 + ty * 4 + i;
#pragma unroll
        for (int j = 0; j < 4; j++) {
            int c = bn0 + tx * 4 + j;
            if (c < N) {
                float v = acc[i][j] + (bias ? bias[c] : 0.f);
                if (do_relu) v = fmaxf(v, 0.f);
                C[(size_t)m * ldc + c] = v;
            }
        }
    }
}

// ---------------------------------------------------------------------------
// fc0a fused: feats[163840,512] @ fc0_w[0:512,:], +g_u[m/5], relu, dot fcs_w,
// atomicAdd into g_score.
// ---------------------------------------------------------------------------
__global__ __launch_bounds__(256) void fc0a_score(
    const float* __restrict__ feats, const float* __restrict__ W,
    const float* __restrict__ fcs_w)
{
    __shared__ float As[16][64];
    __shared__ float Bs[16][64];
    const int tid = threadIdx.x;
    const int tx = tid & 15, ty = tid >> 4;
    const int bm0 = blockIdx.x * 64;
    const int bn0 = blockIdx.y * 64;

    const int aRow = tid >> 2;
    const int aK   = (tid & 3) * 4;
    const int bK   = tid >> 4;
    const int bN   = (tid & 15) * 4;

    float acc[4][4];
#pragma unroll
    for (int i = 0; i < 4; i++)
#pragma unroll
        for (int j = 0; j < 4; j++) acc[i][j] = 0.f;

    const float* Ab = feats + (size_t)(bm0 + aRow) * DIM + aK;

    for (int k0 = 0; k0 < DIM; k0 += 16) {
        float4 av = *(const float4*)(Ab + k0);
        As[aK + 0][aRow] = av.x; As[aK + 1][aRow] = av.y;
        As[aK + 2][aRow] = av.z; As[aK + 3][aRow] = av.w;
        float4 bv = *(const float4*)(W + (size_t)(k0 + bK) * DIM + bn0 + bN);
        *(float4*)&Bs[bK][bN] = bv;
        __syncthreads();
#pragma unroll
        for (int kk = 0; kk < 16; kk++) {
            float4 a = *(const float4*)&As[kk][ty * 4];
            float4 b = *(const float4*)&Bs[kk][tx * 4];
            float ar[4] = {a.x, a.y, a.z, a.w};
            float br[4] = {b.x, b.y, b.z, b.w};
#pragma unroll
            for (int i = 0; i < 4; i++)
#pragma unroll
                for (int j = 0; j < 4; j++) acc[i][j] += ar[i] * br[j];
        }
        __syncthreads();
    }

    float wj[4];
#pragma unroll
    for (int j = 0; j < 4; j++) wj[j] = fcs_w[bn0 + tx * 4 + j];

    float part[4];
#pragma unroll
    for (int i = 0; i < 4; i++) {
        int m = bm0 + ty * 4 + i;
        const float* up = g_u + (size_t)(m / NIMG) * DIM + bn0 + tx * 4;
        float p = 0.f;
#pragma unroll
        for (int j = 0; j < 4; j++) {
            float v = acc[i][j] + up[j];
            v = fmaxf(v, 0.f);
            p += v * wj[j];
        }
        part[i] = p;
    }
#pragma unroll
    for (int off = 8; off >= 1; off >>= 1) {
#pragma unroll
        for (int i = 0; i < 4; i++)
            part[i] += __shfl_xor_sync(0xffffffffu, part[i], off);
    }
    if (tx == 0) {
#pragma unroll
        for (int i = 0; i < 4; i++)
            atomicAdd(&g_score[bm0 + ty * 4 + i], part[i]);
    }
}

__global__ void zero_score()
{
    int i = blockIdx.x * blockDim.x + threadIdx.x;
    if (i < M5) g_score[i] = 0.f;
}

// FLOAT32 output: [score (M5 f32) | rank (M5 f32)] — exactly out_size=2*M5
// f32 elements. Rank = position under descending stable sort (double argsort).
__global__ void finalize_f32(const float* __restrict__ fcs_b, float* __restrict__ out)
{
    int n = blockIdx.x * blockDim.x + threadIdx.x;
    if (n >= BATCH) return;
    float fb = fcs_b[0];
    float s[5];
#pragma unroll
    for (int i = 0; i < 5; i++) s[i] = g_score[n * 5 + i] + fb;
#pragma unroll
    for (int i = 0; i < 5; i++) {
        int si = n * 5 + i;
        out[si] = s[i];
        int r = 0;
#pragma unroll
        for (int j = 0; j < 5; j++)
            r += (s[j] > s[i]) || ((s[j] == s[i]) && (j < i));
        out[M5 + si] = (float)r;
    }
}

extern "C" void kernel_launch(void* const* d_in, const int* in_sizes, int n_in,
                              void* d_out, int out_size)
{
    const float* feats = (const float*)d_in[0];
    const float* w2    = (const float*)d_in[1];
    const float* b2    = (const float*)d_in[2];
    const float* w3    = (const float*)d_in[3];
    const float* b3    = (const float*)d_in[4];
    const float* w5    = (const float*)d_in[5];
    const float* b5    = (const float*)d_in[6];
    const float* fc1_w = (const float*)d_in[7];
    const float* fc1_b = (const float*)d_in[8];
    const float* fc2_w = (const float*)d_in[9];
    const float* fc2_b = (const float*)d_in[10];
    const float* fc0_w = (const float*)d_in[11];
    const float* fc0_b = (const float*)d_in[12];
    const float* fcs_w = (const float*)d_in[13];
    const float* fcs_b = (const float*)d_in[14];

    float *pc, *ph, *pci, *pu;
    cudaGetSymbolAddress((void**)&pc, g_c);
    cudaGetSymbolAddress((void**)&ph, g_h);
    cudaGetSymbolAddress((void**)&pci, g_ci);
    cudaGetSymbolAddress((void**)&pu, g_u);

    dim3 blk(256);

    conv_gemm<<<dim3(BATCH / 64, 4), blk>>>(feats, w2, b2, 2 * DIM, 4, 0);
    conv_gemm<<<dim3(BATCH / 64, 4), blk>>>(feats, w3, b3, 3 * DIM, 3, 200);
    conv_gemm<<<dim3(BATCH / 64, 4), blk>>>(feats, w5, b5, 5 * DIM, 1, 400);

    fc_gemm<<<dim3(BATCH / 64, 10), blk>>>(pc, DCAT, fc1_w, DCAT, fc1_b,
                                           ph, DCAT, DCAT, DCAT, 1);
    fc_gemm<<<dim3(BATCH / 64, 8), blk>>>(ph, DCAT, fc2_w, DIM, fc2_b,
                                          pci, DIM, DIM, DCAT, 0);
    fc_gemm<<<dim3(BATCH / 64, 8), blk>>>(pci, DIM, fc0_w + (size_t)DIM * DIM, DIM,
                                          fc0_b, pu, DIM, DIM, DIM, 0);

    zero_score<<<(M5 + 255) / 256, 256>>>();
    fc0a_score<<<dim3(M5 / 64, 8), blk>>>(feats, fc0_w, fcs_w);

    finalize_f32<<<(BATCH + 255) / 256, 256>>>(fcs_b, (float*)d_out);
}